// round 13
// baseline (speedup 1.0000x reference)
#include <cuda_runtime.h>
#include <cstdint>
#include <math.h>

// CTC batch cost (TF/Keras: blank = last class, lp = log(p + 1e-7)).
// Pair-split forward algorithm: TWO warps per batch element.
//   Warp A: lane l owns states [4l, 4l+4)          (states 0..127)
//   Warp B: lane l owns states [92+4l, 92+4l+4)    (92..103 = redundant halo)
// Info flows left->right only; B recomputes the halo with zeroed left inflow
// (stale spreads 2 states/step -> states 100..103 stay exact each 4-step
// block) and re-adopts A's exact values every block via SMEM + named barrier.
// Numerics: ONE frozen exponent per LANE (4 states), with the frame chosen by
// a DECAYED-MAX SCAN  En(L) = max_k (et(L-k) - 48k)  (Hillis-Steele, 5
// rounds). Scan suffix property => En(L-1) - En(L) <= 48 ALWAYS, so boundary
// alignment factors are <= 2^48 and staged boundary terms are provably
// bounded < 2^127 (the frontier chasm that produced inf in R8/R9/R12 cannot
// occur). Renorm every 4 steps. Rows streamed in 4-row cp.async groups
// through a 3-slot ring; block loop unrolled x3 => addresses [reg + imm].

namespace {
constexpr int kB = 256, kT = 1024, kC = 128, kU = 100;
constexpr int kBlank = kC - 1;     // 127
constexpr float kEps = 1e-7f;
constexpr int PAIRS = 2;           // batch elements per CTA (4 warps)
constexpr int DK = 48;             // frame decay per lane distance
}

__device__ __forceinline__ void cp_async16(void* smem, const void* gmem) {
    unsigned s = (unsigned)__cvta_generic_to_shared(smem);
    asm volatile("cp.async.ca.shared.global [%0], [%1], 16;" :: "r"(s), "l"(gmem));
}
__device__ __forceinline__ void cp_commit() { asm volatile("cp.async.commit_group;"); }
__device__ __forceinline__ void cp_wait2()  { asm volatile("cp.async.wait_group 2;"); }

__global__ __launch_bounds__(PAIRS * 64)
void ctc_kernel(const float* __restrict__ yp, const int* __restrict__ yt,
                const int* __restrict__ ll, float* __restrict__ out)
{
    __shared__ __align__(16) float rows_[PAIRS][12 * kC];  // 3 slots x 4 rows
    __shared__ __align__(16) float hm[PAIRS][3][12];       // halo mantissas
    __shared__ int   he[PAIRS][3][3];                      // halo exponents
    __shared__ __align__(16) float stm[PAIRS][208];        // readout staging
    __shared__ int   ste[PAIRS][52];

    const int lane = threadIdx.x & 31;
    const int warp = threadIdx.x >> 5;
    const int pair = warp >> 1;
    const int role = warp & 1;                 // 0 = A, 1 = B
    const int b = blockIdx.x * PAIRS + pair;
    const float* __restrict__ base = yp + (size_t)b * kT * kC;
    const int barid = 1 + pair;

    float* const rowf = rows_[pair];
    char*  const rbw  = (char*)rowf;

    // ---- static per-lane config --------------------------------------
    const int s0 = role ? (92 + 4 * lane) : (4 * lane);
    const int idx1 = min(s0 >> 1, kU - 1);
    const int idx3 = min((s0 >> 1) + 1, kU - 1);
    const int cls1 = yt[b * kU + idx1];
    const int cls3 = yt[b * kU + idx3];
    const int clsP = yt[b * kU + max(idx1 - 1, 0)];
    const float skA = ((s0 + 1 >= 3) && (cls1 != clsP)) ? 1.f : 0.f;  // state s0+1
    const float skB = (cls3 != cls1) ? 1.f : 0.f;                     // state s0+3

    const float vm0 = (s0     <= 200) ? 1.f : 0.f; const float eps0 = vm0 * kEps;
    const float vm1 = (s0 + 1 <= 200) ? 1.f : 0.f; const float eps1 = vm1 * kEps;
    const float vm2 = (s0 + 2 <= 200) ? 1.f : 0.f; const float eps2 = vm2 * kEps;
    const float vm3 = (s0 + 3 <= 200) ? 1.f : 0.f; const float eps3 = vm3 * kEps;

    const float* const qpB = rowf + kBlank;
    const float* const qp1 = rowf + cls1;
    const float* const qp3 = rowf + cls3;

    float m[4] = {0.f, 0.f, 0.f, 0.f};
    int E = 0;                       // any init is safe: the scan bounds dd
    float fA = 0.f, fB = 0.f, fBs = 0.f;

#define BAR() asm volatile("bar.sync %0, 64;" :: "r"(barid) : "memory")

#define STEP(OFF) do {                                                        \
    float bm1 = __shfl_up_sync(0xffffffffu, m[3], 1);                         \
    float bt = bm1 * fA;                                                      \
    float b1 = bt * fB;                                                       \
    float b2 = bt * fBs;                                                      \
    float pb = qpB[(OFF) >> 2];                                               \
    float p1 = qp1[(OFF) >> 2];                                               \
    float p3 = qp3[(OFF) >> 2];                                               \
    float qb0 = fmaf(pb, vm0, eps0);                                          \
    float q1  = fmaf(p1, vm1, eps1);                                          \
    float qb2 = fmaf(pb, vm2, eps2);                                          \
    float q3  = fmaf(p3, vm3, eps3);                                          \
    float v0 = (m[0] + b1) * qb0;                                             \
    float v1 = ((m[1] + m[0]) + b2) * q1;                                     \
    float v2 = (m[2] + m[1]) * qb2;                                           \
    float v3 = fmaf(skB, m[1], m[3] + m[2]) * q3;                             \
    m[0] = v0; m[1] = v1; m[2] = v2; m[3] = v3;                               \
} while (0)

// Renorm: per-lane true exponent et; frame via decayed-max scan
// Ef(L) = max_k (et(L-k) - DK*k). Suffix property => Ef(L-1) - Ef(L) <= DK.
// Mantissas realigned by two exact power-of-2 multiplies (zeros stay zero;
// deep underflow flushes values > ~175 bits below frame -- pure eps-tails,
// re-seeded exactly when the wavefront arrives). Boundary scales fA*fB =
// 2^(Ef_prev - Ef): upward leg <= 2^48 (exact), downward two-stage.
#define RENORM() do {                                                         \
    float mx = fmaxf(fmaxf(m[0], m[1]), fmaxf(m[2], m[3]));                   \
    int eb = (__float_as_int(mx) >> 23) & 255;                                \
    int Ef = E + eb - 126;                                                    \
    _Pragma("unroll")                                                         \
    for (int o = 1; o <= 16; o <<= 1) {                                       \
        int pe = __shfl_up_sync(0xffffffffu, Ef, o);                          \
        if (lane >= o) Ef = max(Ef, pe - DK * o);                             \
    }                                                                         \
    int dm = E - Ef;                       /* <= 126 - eb by Ef >= et */      \
    int dA_ = min(max(dm, -126), 126);                                        \
    int dB_ = min(max(dm - dA_, -126), 0);                                    \
    float rA = __int_as_float((127 + dA_) << 23);                             \
    float rB = __int_as_float((127 + dB_) << 23);                             \
    m[0] = m[0] * rA * rB; m[1] = m[1] * rA * rB;                             \
    m[2] = m[2] * rA * rB; m[3] = m[3] * rA * rB;                             \
    int Epf = __shfl_up_sync(0xffffffffu, Ef, 1);                             \
    int dd = Epf - Ef;                     /* <= DK by scan suffix */         \
    int eA_ = min(max(dd, -126), 126);                                        \
    int eB_ = min(max(dd - eA_, -126), 0);                                    \
    fA = (lane == 0) ? 0.f : __int_as_float((127 + eA_) << 23);               \
    fB = __int_as_float((127 + eB_) << 23);                                   \
    fBs = fB * skA;                                                           \
    E = Ef;                                                                   \
} while (0)

// One 4-step block k: issue group k+2 into slot PS; wait own groups; BAR
// (rows + halo slot CS visible); B adopts halo CS; renorm; 4 steps on CS;
// A writes halo HS = (k+1)%3 (read by B at block k+1, whose CS == HS).
#define BLOCK(CS, PS, HS, ISSUE) do {                                         \
    if (ISSUE) {                                                              \
        cp_async16(rbw + (PS) * 2048 + role * 1024 +   0 + lane * 16,         \
                   gp +   0);                                                 \
        cp_async16(rbw + (PS) * 2048 + role * 1024 + 512 + lane * 16,         \
                   gp + 512);                                                 \
    }                                                                         \
    cp_commit();                                                              \
    gp += 2048;                                                               \
    cp_wait2();                                                               \
    BAR();                                                                    \
    if (role == 1 && lane < 3) {                                              \
        float4 hv = *(const float4*)&hm[pair][CS][lane * 4];                  \
        m[0] = hv.x; m[1] = hv.y; m[2] = hv.z; m[3] = hv.w;                   \
        E = he[pair][CS][lane];                                               \
    }                                                                         \
    RENORM();                                                                 \
    STEP((CS) * 2048 +    0);                                                 \
    STEP((CS) * 2048 +  512);                                                 \
    STEP((CS) * 2048 + 1024);                                                 \
    STEP((CS) * 2048 + 1536);                                                 \
    if (role == 0 && lane >= 23 && lane <= 25) {                              \
        *(float4*)&hm[pair][HS][(lane - 23) * 4] =                            \
            make_float4(m[0], m[1], m[2], m[3]);                              \
        he[pair][HS][lane - 23] = E;                                          \
    }                                                                         \
} while (0)

    // ---- prologue: groups 0..2 (rows 0..11); each warp loads its half --
    const char* gp = (const char*)base + role * 1024 + lane * 16;
    #pragma unroll
    for (int g = 0; g < 3; ++g) {
        cp_async16(rbw + g * 2048 + role * 1024 +   0 + lane * 16,
                   gp + g * 2048);
        cp_async16(rbw + g * 2048 + role * 1024 + 512 + lane * 16,
                   gp + g * 2048 + 512);
        cp_commit();
    }
    gp += 3 * 2048;
    cp_wait2();        // group 0 landed (this warp's half)
    BAR();             // both halves visible

    // t = 0: only states 0 (blank) and 1 (first label) start nonzero.
    if (role == 0 && lane == 0) {
        m[0] = qpB[0] + kEps;
        m[1] = qp1[0] + kEps;
    }
    RENORM();
    // steps t = 1..3 (rows 1..3 of slot 0)
    STEP(512); STEP(1024); STEP(1536);
    // halo for block 1 (CS = 1)
    if (role == 0 && lane >= 23 && lane <= 25) {
        *(float4*)&hm[pair][1][(lane - 23) * 4] = make_float4(m[0], m[1], m[2], m[3]);
        he[pair][1][lane - 23] = E;
    }

    // ---- main: blocks k = 1..252, unrolled x3 ------------------------
    #pragma unroll 1
    for (int kk = 0; kk < 84; ++kk) {
        BLOCK(1, 0, 2, true);
        BLOCK(2, 1, 0, true);
        BLOCK(0, 2, 1, true);
    }
    // peel k = 253 (issues last group 255), 254, 255 (empty commits)
    BLOCK(1, 0, 2, true);
    BLOCK(2, 1, 0, false);
    BLOCK(0, 2, 1, false);

#undef BLOCK
#undef RENORM
#undef STEP

    // ---- readout ------------------------------------------------------
    if (role == 0 && lane < 26) {              // states 0..103
        *(float4*)&stm[pair][4 * lane] = make_float4(m[0], m[1], m[2], m[3]);
        ste[pair][lane] = E;
    }
    if (role == 1 && lane >= 3 && lane <= 27) {  // states 104..203
        *(float4*)&stm[pair][92 + 4 * lane] = make_float4(m[0], m[1], m[2], m[3]);
        ste[pair][23 + lane] = E;
    }
    BAR();
    if (role == 0 && lane == 0) {
        const int L = ll[b];
        const int end = 2 * L;                       // in [2, 200]
        const float mA_ = stm[pair][end - 1]; const int eA2 = ste[pair][(end - 1) >> 2];
        const float mB_ = stm[pair][end];     const int eB2 = ste[pair][end >> 2];
        const double LN2 = 0.6931471805599453;
        double vA = (mA_ > 0.f) ? log((double)mA_) + (double)eA2 * LN2 : -1e300;
        double vB = (mB_ > 0.f) ? log((double)mB_) + (double)eB2 * LN2 : -1e300;
        double mx2 = fmax(vA, vB);
        out[b] = (float)(-(mx2 + log(exp(vA - mx2) + exp(vB - mx2))));
    }
#undef BAR
}

extern "C" void kernel_launch(void* const* d_in, const int* in_sizes, int n_in,
                              void* d_out, int out_size) {
    const float* y_pred = nullptr;
    const int* y_true = nullptr;
    const int* lab_len = nullptr;
    for (int i = 0; i < n_in; ++i) {
        if (in_sizes[i] == kB * kT * kC)      y_pred  = (const float*)d_in[i];
        else if (in_sizes[i] == kB * kU)      y_true  = (const int*)d_in[i];
        else if (in_sizes[i] == kB)           lab_len = (const int*)d_in[i];
    }
    float* out = (float*)d_out;
    (void)out_size;
    ctc_kernel<<<kB / PAIRS, PAIRS * 64>>>(y_pred, y_true, lab_len, out);
}

// round 16
// speedup vs baseline: 1.1666x; 1.1666x over previous
#include <cuda_runtime.h>
#include <cstdint>
#include <math.h>

// CTC batch cost (TF/Keras: blank = last class, lp = log(p + 1e-7)).
// R10's twice-validated numerics, verbatim: BLOCK-FROZEN extended-range
// arithmetic, value[s] = m[s] * 2^E[s]; per-state exponents frozen per 4-step
// block at the max true exponent over the left window [s-8, s]; alignment
// factors s1/s2 are block-constant clamped powers of 2 (downward-safe).
//   m[s] <- (m[s] + s1*m[s-1] + s2*m[s-2]) * q     (blanks: no s2 term)
// One WARP per batch element; lane L owns states [8L, 8L+8); alpha in
// registers. NEW this round (mechanical only, zero arithmetic change):
// the cross-step boundary shuffle is SOFTWARE-PIPELINED -- v7 is computed
// first, m[7] written, and the next step's shfl issued immediately so its
// 26-cycle latency overlaps the remaining 7 state updates, removing the
// ~58-cycle serial boundary chain from the critical path. q-loads hoisted
// to the top of each step. Rows streamed in 4-row cp.async groups through
// a 3-slot ring; block loop unrolled x3 (all smem addresses [reg + imm]).

namespace {
constexpr int kB = 256, kT = 1024, kC = 128, kU = 100;
constexpr int kBlank = kC - 1;     // 127
constexpr float kEps = 1e-7f;
constexpr int WPB  = 2;            // warps (batch elements) per CTA
constexpr int NLANE = 26;          // lanes carrying valid states
constexpr int E0   = -(1 << 24);   // initial exponent for empty states
constexpr int EMIN = -(1 << 30);   // lane-0 boundary "minus infinity"
}

__device__ __forceinline__ void cp_async16(void* smem, const void* gmem) {
    unsigned s = (unsigned)__cvta_generic_to_shared(smem);
    asm volatile("cp.async.ca.shared.global [%0], [%1], 16;" :: "r"(s), "l"(gmem));
}
__device__ __forceinline__ void cp_commit() { asm volatile("cp.async.commit_group;"); }
__device__ __forceinline__ void cp_wait2()  { asm volatile("cp.async.wait_group 2;"); }

// 2^d as float, clamped: d <= -127 -> 0, d >= 126 -> 2^126. Pure ALU.
__device__ __forceinline__ float pow2s(int d) {
    d = min(d, 126); d = max(d, -200);
    return __int_as_float(max((127 + d) << 23, 0));
}
// m * 2^d for d <= 0, flushing results below ~2^-126 to zero.
__device__ __forceinline__ float scale_down(float m, int d) {
    d = max(d, -220);
    return __int_as_float(max(__float_as_int(m) + (d << 23), 0));
}

__global__ __launch_bounds__(WPB * 32)
void ctc_kernel(const float* __restrict__ yp, const int* __restrict__ yt,
                const int* __restrict__ ll, float* __restrict__ out)
{
    __shared__ __align__(16) float prow[WPB][12 * kC];  // 3 slots x 4 rows
    __shared__ float stm[WPB][NLANE * 8];
    __shared__ int   ste[WPB][NLANE * 8];

    const int warp = threadIdx.x >> 5;
    const int lane = threadIdx.x & 31;
    const int b = blockIdx.x * WPB + warp;
    const float* __restrict__ base = yp + (size_t)b * kT * kC;

    float* const rowf = prow[warp];
    char*  const rbw  = (char*)rowf;

    // ---- static per-lane config (verbatim R10) ------------------------
    // s = 8*lane + j; even j -> blank, odd -> label. Indices clamped; out-of-
    // range lanes' garbage flows only to HIGHER lanes (shfl_up) -- harmless.
    const int s0 = lane * 8;
    int cls[4]; bool skipg[4];
    #pragma unroll
    for (int jj = 0; jj < 4; ++jj) {
        const int s = s0 + 2 * jj + 1;
        const int idx = min(s >> 1, kU - 1);
        const int c = yt[b * kU + idx];
        cls[jj] = c;
        skipg[jj] = (s >= 3) && (c != yt[b * kU + max(idx - 1, 0)]);
    }

    // hoisted q base pointers (row 0 of slot 0); step offsets are immediates
    const float* const qpB = rowf + kBlank;
    const float* const qp1 = rowf + cls[0];
    const float* const qp3 = rowf + cls[1];
    const float* const qp5 = rowf + cls[2];
    const float* const qp7 = rowf + cls[3];

    float m[8]; int E[8]; float s1[8]; float s2o[4];
    #pragma unroll
    for (int j = 0; j < 8; ++j) { m[j] = 0.f; E[j] = E0; }
    float bm1 = 0.f;   // pipelined boundary value (prev lane's m[7], prev step)

    // Renorm (verbatim R10): recompute true exponents, window-max freeze,
    // realign mantissas, rebuild block-constant scales.
    auto renorm = [&]() {
        int et[8];
        #pragma unroll
        for (int j = 0; j < 8; ++j) {
            const int vi = __float_as_int(m[j]);
            const int f = (vi >> 23) & 255;
            et[j] = vi ? (E[j] + f - 126) : (E[j] - 4096);   // zeros decay fast
            m[j] = __int_as_float((vi & 0x807FFFFF) | (vi ? (126 << 23) : 0));
        }
        int pre[8], suf[8];
        pre[0] = et[0];
        #pragma unroll
        for (int j = 1; j < 8; ++j) pre[j] = max(pre[j - 1], et[j]);
        suf[7] = et[7];
        #pragma unroll
        for (int j = 6; j >= 0; --j) suf[j] = max(suf[j + 1], et[j]);

        int En[8];
        #pragma unroll
        for (int j = 0; j < 8; ++j) {
            int ps = __shfl_up_sync(0xffffffffu, suf[j], 1);
            if (lane == 0) ps = EMIN;
            En[j] = max(pre[j], ps);          // window max over states [s-8, s]
        }
        int pE7 = __shfl_up_sync(0xffffffffu, En[7], 1);
        if (lane == 0) pE7 = EMIN;

        #pragma unroll
        for (int j = 0; j < 8; ++j) m[j] = scale_down(m[j], et[j] - En[j]);

        s1[0] = (lane == 0) ? 0.f : pow2s(pE7 - En[0]);
        #pragma unroll
        for (int j = 1; j < 8; ++j) s1[j] = pow2s(En[j - 1] - En[j]);
        s2o[0] = skipg[0] ? pow2s(pE7   - En[1]) : 0.f;
        s2o[1] = skipg[1] ? pow2s(En[1] - En[3]) : 0.f;
        s2o[2] = skipg[2] ? pow2s(En[3] - En[5]) : 0.f;
        s2o[3] = skipg[3] ? pow2s(En[5] - En[7]) : 0.f;
        #pragma unroll
        for (int j = 0; j < 8; ++j) E[j] = En[j];
    };

// Pipelined step: identical arithmetic to R10; v7 computed FIRST and the
// next step's boundary shuffle issued immediately so its latency overlaps
// the remaining 7 state updates. bm1 holds prev lane's m[7] from the
// PREVIOUS step (refreshed after every renorm).
#define STEP(OFF) do {                                                        \
    float qb = qpB[(OFF) >> 2] + kEps;                                        \
    float q1 = qp1[(OFF) >> 2] + kEps;                                        \
    float q3 = qp3[(OFF) >> 2] + kEps;                                        \
    float q5 = qp5[(OFF) >> 2] + kEps;                                        \
    float q7 = qp7[(OFF) >> 2] + kEps;                                        \
    float v7 = fmaf(s2o[3], m[5], fmaf(s1[7], m[6], m[7])) * q7;              \
    m[7] = v7;                                                                \
    float bm1n = __shfl_up_sync(0xffffffffu, m[7], 1);                        \
    float v6 = fmaf(s1[6], m[5], m[6]) * qb;                                  \
    float v5 = fmaf(s2o[2], m[3], fmaf(s1[5], m[4], m[5])) * q5;              \
    float v4 = fmaf(s1[4], m[3], m[4]) * qb;                                  \
    float v3 = fmaf(s2o[1], m[1], fmaf(s1[3], m[2], m[3])) * q3;              \
    float v2 = fmaf(s1[2], m[1], m[2]) * qb;                                  \
    float v1 = fmaf(s2o[0], bm1, fmaf(s1[1], m[0], m[1])) * q1;               \
    float v0 = fmaf(s1[0], bm1, m[0]) * qb;                                   \
    m[0] = v0; m[1] = v1; m[2] = v2; m[3] = v3;                               \
    m[4] = v4; m[5] = v5; m[6] = v6;                                          \
    bm1 = bm1n;                                                               \
} while (0)

// One 4-step block: issue next group into slot PS; renorm hidden between
// commit and wait; refresh the pipelined boundary (renorm realigned m[7]);
// 4 steps on slot CS.
#define BLOCK(CS, PS, ISSUE) do {                                             \
    if (ISSUE) {                                                              \
        cp_async16(rbw + (PS) * 2048 +    0 + lane * 16, gp +    0);          \
        cp_async16(rbw + (PS) * 2048 +  512 + lane * 16, gp +  512);          \
        cp_async16(rbw + (PS) * 2048 + 1024 + lane * 16, gp + 1024);          \
        cp_async16(rbw + (PS) * 2048 + 1536 + lane * 16, gp + 1536);          \
    }                                                                         \
    cp_commit();                                                              \
    gp += 2048;                                                               \
    renorm();                                                                 \
    bm1 = __shfl_up_sync(0xffffffffu, m[7], 1);                               \
    cp_wait2();                                                               \
    __syncwarp();                                                             \
    STEP((CS) * 2048 +    0);                                                 \
    STEP((CS) * 2048 +  512);                                                 \
    STEP((CS) * 2048 + 1024);                                                 \
    STEP((CS) * 2048 + 1536);                                                 \
} while (0)

    // ---- prologue: groups 0..2 (rows 0..11) --------------------------
    const char* gp = (const char*)base + lane * 16;
    #pragma unroll
    for (int g = 0; g < 3; ++g) {
        #pragma unroll
        for (int r = 0; r < 4; ++r)
            cp_async16(rbw + g * 2048 + r * 512 + lane * 16,
                       gp + g * 2048 + r * 512);
        cp_commit();
    }
    gp += 3 * 2048;
    cp_wait2();        // group 0 landed
    __syncwarp();

    // t = 0: only states 0 (blank) and 1 (first label) start nonzero.
    if (lane == 0) {
        m[0] = qpB[0] + kEps;  E[0] = 0;
        m[1] = qp1[0] + kEps;  E[1] = 0;
    }
    renorm();          // set up s1/s2o for steps 1..3 (as in R10)
    bm1 = __shfl_up_sync(0xffffffffu, m[7], 1);
    // steps t = 1..3 (rows 1..3, slot 0)
    STEP(512); STEP(1024); STEP(1536);

    // ---- main: blocks k = 1..252, unrolled x3 ------------------------
    #pragma unroll 1
    for (int kk = 0; kk < 84; ++kk) {
        BLOCK(1, 0, true);
        BLOCK(2, 1, true);
        BLOCK(0, 2, true);
    }
    // peel k = 253 (issues last group 255), 254, 255 (empty commits)
    BLOCK(1, 0, true);
    BLOCK(2, 1, false);
    BLOCK(0, 2, false);

#undef BLOCK
#undef STEP

    // ---- readout (verbatim R10) ----------------------------------------
    if (lane < NLANE) {
        #pragma unroll
        for (int j = 0; j < 8; ++j) {
            stm[warp][lane * 8 + j] = m[j];
            ste[warp][lane * 8 + j] = E[j];
        }
    }
    __syncwarp();
    if (lane == 0) {
        const int L = ll[b];
        const int end = 2 * L;                       // in [2, 200]
        const float mA = stm[warp][end - 1]; const int eA = ste[warp][end - 1];
        const float mB = stm[warp][end];     const int eB = ste[warp][end];
        const double LN2 = 0.6931471805599453;
        double vA = (mA > 0.f) ? log((double)mA) + (double)eA * LN2 : -1e300;
        double vB = (mB > 0.f) ? log((double)mB) + (double)eB * LN2 : -1e300;
        double mx = fmax(vA, vB);
        out[b] = (float)(-(mx + log(exp(vA - mx) + exp(vB - mx))));
    }
}

extern "C" void kernel_launch(void* const* d_in, const int* in_sizes, int n_in,
                              void* d_out, int out_size) {
    const float* y_pred = nullptr;
    const int* y_true = nullptr;
    const int* lab_len = nullptr;
    for (int i = 0; i < n_in; ++i) {
        if (in_sizes[i] == kB * kT * kC)      y_pred  = (const float*)d_in[i];
        else if (in_sizes[i] == kB * kU)      y_true  = (const int*)d_in[i];
        else if (in_sizes[i] == kB)           lab_len = (const int*)d_in[i];
    }
    float* out = (float*)d_out;
    (void)out_size;
    ctc_kernel<<<kB / WPB, WPB * 32>>>(y_pred, y_true, lab_len, out);
}

// round 17
// speedup vs baseline: 1.2643x; 1.0837x over previous
#include <cuda_runtime.h>
#include <cstdint>
#include <math.h>

// CTC batch cost (TF/Keras: blank = last class, lp = log(p + 1e-7)).
// R10's thrice-validated numerics, verbatim: BLOCK-FROZEN extended-range
// arithmetic, value[s] = m[s] * 2^E[s]; per-state exponents frozen per 4-step
// block at the max true exponent over the left window [s-8, s]; alignment
// factors s1/s2 are block-constant clamped powers of 2 (downward-safe).
//   m[s] <- (m[s] + s1*m[s-1] + s2*m[s-2]) * q     (blanks: no s2 term)
// One WARP per batch element; lane L owns states [8L, 8L+8); alpha in
// registers; pipelined boundary shuffle (R16). NEW this round (pure
// scheduling, zero arithmetic change): all 20 q-loads of a block are hoisted
// to right after cp_wait/syncwarp and issued BEFORE renorm, so the renorm's
// ~60-100-cycle serial chain hides their LDS latency and the 4 steps run
// stall-free. Rows streamed in 4-row cp.async groups through a 3-slot ring;
// block loop unrolled x3 (all smem addresses [reg + immediate]).

namespace {
constexpr int kB = 256, kT = 1024, kC = 128, kU = 100;
constexpr int kBlank = kC - 1;     // 127
constexpr float kEps = 1e-7f;
constexpr int WPB  = 2;            // warps (batch elements) per CTA
constexpr int NLANE = 26;          // lanes carrying valid states
constexpr int E0   = -(1 << 24);   // initial exponent for empty states
constexpr int EMIN = -(1 << 30);   // lane-0 boundary "minus infinity"
}

__device__ __forceinline__ void cp_async16(void* smem, const void* gmem) {
    unsigned s = (unsigned)__cvta_generic_to_shared(smem);
    asm volatile("cp.async.ca.shared.global [%0], [%1], 16;" :: "r"(s), "l"(gmem));
}
__device__ __forceinline__ void cp_commit() { asm volatile("cp.async.commit_group;"); }
__device__ __forceinline__ void cp_wait2()  { asm volatile("cp.async.wait_group 2;"); }

// 2^d as float, clamped: d <= -127 -> 0, d >= 126 -> 2^126. Pure ALU.
__device__ __forceinline__ float pow2s(int d) {
    d = min(d, 126); d = max(d, -200);
    return __int_as_float(max((127 + d) << 23, 0));
}
// m * 2^d for d <= 0, flushing results below ~2^-126 to zero.
__device__ __forceinline__ float scale_down(float m, int d) {
    d = max(d, -220);
    return __int_as_float(max(__float_as_int(m) + (d << 23), 0));
}

__global__ __launch_bounds__(WPB * 32)
void ctc_kernel(const float* __restrict__ yp, const int* __restrict__ yt,
                const int* __restrict__ ll, float* __restrict__ out)
{
    __shared__ __align__(16) float prow[WPB][12 * kC];  // 3 slots x 4 rows
    __shared__ float stm[WPB][NLANE * 8];
    __shared__ int   ste[WPB][NLANE * 8];

    const int warp = threadIdx.x >> 5;
    const int lane = threadIdx.x & 31;
    const int b = blockIdx.x * WPB + warp;
    const float* __restrict__ base = yp + (size_t)b * kT * kC;

    float* const rowf = prow[warp];
    char*  const rbw  = (char*)rowf;

    // ---- static per-lane config (verbatim R10) ------------------------
    const int s0 = lane * 8;
    int cls[4]; bool skipg[4];
    #pragma unroll
    for (int jj = 0; jj < 4; ++jj) {
        const int s = s0 + 2 * jj + 1;
        const int idx = min(s >> 1, kU - 1);
        const int c = yt[b * kU + idx];
        cls[jj] = c;
        skipg[jj] = (s >= 3) && (c != yt[b * kU + max(idx - 1, 0)]);
    }

    // hoisted q base pointers (row 0 of slot 0); step offsets are immediates
    const float* const qpB = rowf + kBlank;
    const float* const qp1 = rowf + cls[0];
    const float* const qp3 = rowf + cls[1];
    const float* const qp5 = rowf + cls[2];
    const float* const qp7 = rowf + cls[3];

    float m[8]; int E[8]; float s1[8]; float s2o[4];
    #pragma unroll
    for (int j = 0; j < 8; ++j) { m[j] = 0.f; E[j] = E0; }
    float bm1 = 0.f;   // pipelined boundary value (prev lane's m[7], prev step)

    // Renorm (verbatim R10): recompute true exponents, window-max freeze,
    // realign mantissas, rebuild block-constant scales.
    auto renorm = [&]() {
        int et[8];
        #pragma unroll
        for (int j = 0; j < 8; ++j) {
            const int vi = __float_as_int(m[j]);
            const int f = (vi >> 23) & 255;
            et[j] = vi ? (E[j] + f - 126) : (E[j] - 4096);   // zeros decay fast
            m[j] = __int_as_float((vi & 0x807FFFFF) | (vi ? (126 << 23) : 0));
        }
        int pre[8], suf[8];
        pre[0] = et[0];
        #pragma unroll
        for (int j = 1; j < 8; ++j) pre[j] = max(pre[j - 1], et[j]);
        suf[7] = et[7];
        #pragma unroll
        for (int j = 6; j >= 0; --j) suf[j] = max(suf[j + 1], et[j]);

        int En[8];
        #pragma unroll
        for (int j = 0; j < 8; ++j) {
            int ps = __shfl_up_sync(0xffffffffu, suf[j], 1);
            if (lane == 0) ps = EMIN;
            En[j] = max(pre[j], ps);          // window max over states [s-8, s]
        }
        int pE7 = __shfl_up_sync(0xffffffffu, En[7], 1);
        if (lane == 0) pE7 = EMIN;

        #pragma unroll
        for (int j = 0; j < 8; ++j) m[j] = scale_down(m[j], et[j] - En[j]);

        s1[0] = (lane == 0) ? 0.f : pow2s(pE7 - En[0]);
        #pragma unroll
        for (int j = 1; j < 8; ++j) s1[j] = pow2s(En[j - 1] - En[j]);
        s2o[0] = skipg[0] ? pow2s(pE7   - En[1]) : 0.f;
        s2o[1] = skipg[1] ? pow2s(En[1] - En[3]) : 0.f;
        s2o[2] = skipg[2] ? pow2s(En[3] - En[5]) : 0.f;
        s2o[3] = skipg[3] ? pow2s(En[5] - En[7]) : 0.f;
        #pragma unroll
        for (int j = 0; j < 8; ++j) E[j] = En[j];
    };

// Load the 5 q-values (+eps, identical FADD to before) for one step.
#define LOADQ(Q, OFF) do {                                                    \
    Q[0] = qpB[(OFF) >> 2] + kEps;                                            \
    Q[1] = qp1[(OFF) >> 2] + kEps;                                            \
    Q[2] = qp3[(OFF) >> 2] + kEps;                                            \
    Q[3] = qp5[(OFF) >> 2] + kEps;                                            \
    Q[4] = qp7[(OFF) >> 2] + kEps;                                            \
} while (0)

// Pipelined step on preloaded q's: arithmetic identical to R10/R16.
#define STEPQ(Q) do {                                                         \
    float v7 = fmaf(s2o[3], m[5], fmaf(s1[7], m[6], m[7])) * Q[4];            \
    m[7] = v7;                                                                \
    float bm1n = __shfl_up_sync(0xffffffffu, m[7], 1);                        \
    float v6 = fmaf(s1[6], m[5], m[6]) * Q[0];                                \
    float v5 = fmaf(s2o[2], m[3], fmaf(s1[5], m[4], m[5])) * Q[3];            \
    float v4 = fmaf(s1[4], m[3], m[4]) * Q[0];                                \
    float v3 = fmaf(s2o[1], m[1], fmaf(s1[3], m[2], m[3])) * Q[2];            \
    float v2 = fmaf(s1[2], m[1], m[2]) * Q[0];                                \
    float v1 = fmaf(s2o[0], bm1, fmaf(s1[1], m[0], m[1])) * Q[1];             \
    float v0 = fmaf(s1[0], bm1, m[0]) * Q[0];                                 \
    m[0] = v0; m[1] = v1; m[2] = v2; m[3] = v3;                               \
    m[4] = v4; m[5] = v5; m[6] = v6;                                          \
    bm1 = bm1n;                                                               \
} while (0)

// One 4-step block: issue next group into slot PS; wait (instant -- data
// landed 2 blocks ago) + syncwarp; hoist ALL 20 q-loads; renorm (hides LDS
// latency); refresh pipelined boundary; 4 stall-free steps on slot CS.
#define BLOCK(CS, PS, ISSUE) do {                                             \
    if (ISSUE) {                                                              \
        cp_async16(rbw + (PS) * 2048 +    0 + lane * 16, gp +    0);          \
        cp_async16(rbw + (PS) * 2048 +  512 + lane * 16, gp +  512);          \
        cp_async16(rbw + (PS) * 2048 + 1024 + lane * 16, gp + 1024);          \
        cp_async16(rbw + (PS) * 2048 + 1536 + lane * 16, gp + 1536);          \
    }                                                                         \
    cp_commit();                                                              \
    gp += 2048;                                                               \
    cp_wait2();                                                               \
    __syncwarp();                                                             \
    float qa_[5], qb_[5], qc_[5], qd_[5];                                     \
    LOADQ(qa_, (CS) * 2048 +    0);                                           \
    LOADQ(qb_, (CS) * 2048 +  512);                                           \
    LOADQ(qc_, (CS) * 2048 + 1024);                                           \
    LOADQ(qd_, (CS) * 2048 + 1536);                                           \
    renorm();                                                                 \
    bm1 = __shfl_up_sync(0xffffffffu, m[7], 1);                               \
    STEPQ(qa_); STEPQ(qb_); STEPQ(qc_); STEPQ(qd_);                           \
} while (0)

    // ---- prologue: groups 0..2 (rows 0..11) --------------------------
    const char* gp = (const char*)base + lane * 16;
    #pragma unroll
    for (int g = 0; g < 3; ++g) {
        #pragma unroll
        for (int r = 0; r < 4; ++r)
            cp_async16(rbw + g * 2048 + r * 512 + lane * 16,
                       gp + g * 2048 + r * 512);
        cp_commit();
    }
    gp += 3 * 2048;
    cp_wait2();        // group 0 landed
    __syncwarp();

    // t = 0: only states 0 (blank) and 1 (first label) start nonzero.
    if (lane == 0) {
        m[0] = qpB[0] + kEps;  E[0] = 0;
        m[1] = qp1[0] + kEps;  E[1] = 0;
    }
    {
        float qa_[5], qb_[5], qc_[5];
        LOADQ(qa_, 512); LOADQ(qb_, 1024); LOADQ(qc_, 1536);
        renorm();      // set up s1/s2o for steps 1..3 (as in R10)
        bm1 = __shfl_up_sync(0xffffffffu, m[7], 1);
        STEPQ(qa_); STEPQ(qb_); STEPQ(qc_);
    }

    // ---- main: blocks k = 1..252, unrolled x3 ------------------------
    #pragma unroll 1
    for (int kk = 0; kk < 84; ++kk) {
        BLOCK(1, 0, true);
        BLOCK(2, 1, true);
        BLOCK(0, 2, true);
    }
    // peel k = 253 (issues last group 255), 254, 255 (empty commits)
    BLOCK(1, 0, true);
    BLOCK(2, 1, false);
    BLOCK(0, 2, false);

#undef BLOCK
#undef STEPQ
#undef LOADQ

    // ---- readout (verbatim R10) ----------------------------------------
    if (lane < NLANE) {
        #pragma unroll
        for (int j = 0; j < 8; ++j) {
            stm[warp][lane * 8 + j] = m[j];
            ste[warp][lane * 8 + j] = E[j];
        }
    }
    __syncwarp();
    if (lane == 0) {
        const int L = ll[b];
        const int end = 2 * L;                       // in [2, 200]
        const float mA = stm[warp][end - 1]; const int eA = ste[warp][end - 1];
        const float mB = stm[warp][end];     const int eB = ste[warp][end];
        const double LN2 = 0.6931471805599453;
        double vA = (mA > 0.f) ? log((double)mA) + (double)eA * LN2 : -1e300;
        double vB = (mB > 0.f) ? log((double)mB) + (double)eB * LN2 : -1e300;
        double mx = fmax(vA, vB);
        out[b] = (float)(-(mx + log(exp(vA - mx) + exp(vB - mx))));
    }
}

extern "C" void kernel_launch(void* const* d_in, const int* in_sizes, int n_in,
                              void* d_out, int out_size) {
    const float* y_pred = nullptr;
    const int* y_true = nullptr;
    const int* lab_len = nullptr;
    for (int i = 0; i < n_in; ++i) {
        if (in_sizes[i] == kB * kT * kC)      y_pred  = (const float*)d_in[i];
        else if (in_sizes[i] == kB * kU)      y_true  = (const int*)d_in[i];
        else if (in_sizes[i] == kB)           lab_len = (const int*)d_in[i];
    }
    float* out = (float*)d_out;
    (void)out_size;
    ctc_kernel<<<kB / WPB, WPB * 32>>>(y_pred, y_true, lab_len, out);
}